// round 4
// baseline (speedup 1.0000x reference)
#include <cuda_runtime.h>
#include <cuda_bf16.h>

#define N_SEQ   256
#define M_GENES 2000
#define D_DIM   128
#define N_NUC   4

#define MT 16                 // genes per tile
#define NT 64                 // sequences per tile
#define M_TILES (M_GENES / MT)   // 125
#define N_TILES (N_SEQ / NT)     // 4
#define SEG_ROWS (MT * N_NUC)    // 64 table rows per tile

// Fused kernel: one block = (NT sequences x MT genes) output tile.
// Phase 1: load + normalize the MT-gene table segment into smem (32 KB).
// Phase 2: gather indices from smem, stream 512B rows to gmem.
__global__ void __launch_bounds__(256) fused_gather_kernel(
        const int* __restrict__ seq,
        const float* __restrict__ emb,
        float* __restrict__ out) {
    __shared__ float s_tab[SEG_ROWS * D_DIM];   // 32 KB
    __shared__ int   s_idx[NT * MT];            // 4 KB

    const unsigned int mt = blockIdx.x % M_TILES;
    const unsigned int nt = blockIdx.x / M_TILES;
    const unsigned int m0 = mt * MT;
    const unsigned int n0 = nt * NT;
    const unsigned int tid  = threadIdx.x;
    const unsigned int warp = tid >> 5;
    const unsigned int lane = tid & 31u;

    // ---- Load indices for the tile: NT*MT = 1024 ints, coalesced ----
    #pragma unroll
    for (int i = 0; i < (NT * MT) / 256; i++) {
        int k = i * 256 + tid;            // k = n_local * MT + m_local
        int n = k / MT, m = k % MT;
        s_idx[k] = __ldg(seq + (size_t)(n0 + n) * M_GENES + m0 + m);
    }

    // ---- Load + normalize SEG_ROWS table rows into smem ----
    // Row r of segment = emb row (m0*N_NUC + r). One warp per row, 8 rows/warp.
    #pragma unroll
    for (int r = warp; r < SEG_ROWS; r += 8) {
        const float4* src = reinterpret_cast<const float4*>(
            emb + (size_t)(m0 * N_NUC + r) * D_DIM);
        float4 v = __ldg(src + lane);
        float ss = v.x * v.x + v.y * v.y + v.z * v.z + v.w * v.w;
        #pragma unroll
        for (int o = 16; o > 0; o >>= 1)
            ss += __shfl_xor_sync(0xffffffffu, ss, o);
        float inv = 1.0f / fmaxf(sqrtf(ss), 1e-12f);
        v.x *= inv; v.y *= inv; v.z *= inv; v.w *= inv;
        reinterpret_cast<float4*>(s_tab + r * D_DIM)[lane] = v;
    }
    __syncthreads();

    // ---- Gather + stream out. Warp w serves n = n0 + w*8 .. +7, all MT genes.
    // Each (n,m) row is 512 B contiguous; per-n the MT rows form 8 KB contiguous.
    for (int nn = 0; nn < NT / 8; nn++) {
        const int nloc = warp * (NT / 8) + nn;
        float4* dst = reinterpret_cast<float4*>(
            out + ((size_t)(n0 + nloc) * M_GENES + m0) * D_DIM) + lane;
        const int* idx = s_idx + nloc * MT;
        #pragma unroll
        for (int m = 0; m < MT; m++) {
            int g = idx[m];                      // warp-uniform LDS broadcast
            float4 v = reinterpret_cast<const float4*>(
                s_tab + (m * N_NUC + g) * D_DIM)[lane];
            __stcs(dst + (size_t)m * 32, v);     // streaming: output never re-read
        }
    }
}

extern "C" void kernel_launch(void* const* d_in, const int* in_sizes, int n_in,
                              void* d_out, int out_size) {
    const int*   gene_seq = (const int*)d_in[0];     // (256, 2000) int32
    const float* emb      = (const float*)d_in[1];   // (2000, 4, 128) f32
    float*       out      = (float*)d_out;           // (256, 2000, 128) f32

    fused_gather_kernel<<<M_TILES * N_TILES, 256>>>(gene_seq, emb, out);
}

// round 5
// speedup vs baseline: 1.6733x; 1.6733x over previous
#include <cuda_runtime.h>
#include <cuda_bf16.h>

#define N_SEQ   256
#define M_GENES 2000
#define D_DIM   128
#define N_NUC   4
#define NG      32                      // sequences handled per warp
#define N_GROUPS (N_SEQ / NG)           // 8
#define TOTAL_WARPS (M_GENES * N_GROUPS)   // 16000
#define WARPS_PER_BLOCK 8

// Component-wise select helpers (compile to SEL, no local memory)
__device__ __forceinline__ float4 sel4(bool p, const float4 a, const float4 b) {
    float4 r;
    r.x = p ? a.x : b.x;
    r.y = p ? a.y : b.y;
    r.z = p ? a.z : b.z;
    r.w = p ? a.w : b.w;
    return r;
}

// Fully fused: normalize-on-the-fly + gather + stream out.
// One warp owns one gene m and NG sequences: the 4 candidate (nucleotide)
// vectors live in registers; each output row is a register select + STG.128.
__global__ void __launch_bounds__(256) fused_kernel(
        const int* __restrict__ seq,
        const float* __restrict__ emb,
        float* __restrict__ out) {
    const unsigned int wid  = (blockIdx.x * blockDim.x + threadIdx.x) >> 5;
    const unsigned int lane = threadIdx.x & 31u;
    const unsigned int m  = wid % M_GENES;       // consecutive warps -> adjacent m
    const unsigned int ng = wid / M_GENES;       // 0..7
    const unsigned int n0 = ng * NG;

    // ---- Load the 4 candidate vectors for gene m (2 KB, contiguous) ----
    const float4* tab = reinterpret_cast<const float4*>(
        emb + (size_t)m * N_NUC * D_DIM);
    float4 v0 = __ldg(tab + 0 * 32 + lane);
    float4 v1 = __ldg(tab + 1 * 32 + lane);
    float4 v2 = __ldg(tab + 2 * 32 + lane);
    float4 v3 = __ldg(tab + 3 * 32 + lane);

    // ---- Indices for this warp's NG sequences (one per lane) ----
    int gidx = __ldg(seq + (size_t)(n0 + lane) * M_GENES + m);

    // ---- Normalize the 4 vectors in registers (warp allreduce each) ----
    {
        float s0 = v0.x*v0.x + v0.y*v0.y + v0.z*v0.z + v0.w*v0.w;
        float s1 = v1.x*v1.x + v1.y*v1.y + v1.z*v1.z + v1.w*v1.w;
        float s2 = v2.x*v2.x + v2.y*v2.y + v2.z*v2.z + v2.w*v2.w;
        float s3 = v3.x*v3.x + v3.y*v3.y + v3.z*v3.z + v3.w*v3.w;
        #pragma unroll
        for (int o = 16; o > 0; o >>= 1) {
            s0 += __shfl_xor_sync(0xffffffffu, s0, o);
            s1 += __shfl_xor_sync(0xffffffffu, s1, o);
            s2 += __shfl_xor_sync(0xffffffffu, s2, o);
            s3 += __shfl_xor_sync(0xffffffffu, s3, o);
        }
        float i0 = 1.0f / fmaxf(sqrtf(s0), 1e-12f);
        float i1 = 1.0f / fmaxf(sqrtf(s1), 1e-12f);
        float i2 = 1.0f / fmaxf(sqrtf(s2), 1e-12f);
        float i3 = 1.0f / fmaxf(sqrtf(s3), 1e-12f);
        v0.x *= i0; v0.y *= i0; v0.z *= i0; v0.w *= i0;
        v1.x *= i1; v1.y *= i1; v1.z *= i1; v1.w *= i1;
        v2.x *= i2; v2.y *= i2; v2.z *= i2; v2.w *= i2;
        v3.x *= i3; v3.y *= i3; v3.z *= i3; v3.w *= i3;
    }

    // ---- Emit NG rows: shfl index -> register select -> streaming STG.128 ----
    float4* dst = reinterpret_cast<float4*>(
        out + ((size_t)n0 * M_GENES + m) * D_DIM) + lane;
    const size_t row_stride = (size_t)M_GENES * (D_DIM / 4);   // float4 units

    #pragma unroll
    for (int nn = 0; nn < NG; nn++) {
        int g = __shfl_sync(0xffffffffu, gidx, nn);
        bool b0 = (g & 1) != 0;
        bool b1 = (g & 2) != 0;
        float4 ab = sel4(b0, v1, v0);
        float4 cd = sel4(b0, v3, v2);
        float4 r  = sel4(b1, cd, ab);
        __stcs(dst, r);                 // output never re-read
        dst += row_stride;
    }
}

extern "C" void kernel_launch(void* const* d_in, const int* in_sizes, int n_in,
                              void* d_out, int out_size) {
    const int*   gene_seq = (const int*)d_in[0];     // (256, 2000) int32
    const float* emb      = (const float*)d_in[1];   // (2000, 4, 128) f32
    float*       out      = (float*)d_out;           // (256, 2000, 128) f32

    fused_kernel<<<TOTAL_WARPS / WARPS_PER_BLOCK, WARPS_PER_BLOCK * 32>>>(
        gene_seq, emb, out);
}